// round 3
// baseline (speedup 1.0000x reference)
#include <cuda_runtime.h>
#include <cuda_bf16.h>
#include <cstddef>

// Problem constants
#define NB   16          // batch
#define CIN  256         // input channels
#define WD   128         // width = CIN/2
#define SP   4096        // spatial = 64*64
#define KSPLIT 8         // split-K factor for kv GEMM (4096/512)

// ---- scratch (device globals; no allocation allowed) ----
__device__ float g_theta[(size_t)NB * WD * SP];
__device__ float g_phi  [(size_t)NB * WD * SP];
__device__ float g_g    [(size_t)NB * WD * SP];
__device__ float g_kvp  [(size_t)NB * KSPLIT * WD * WD];
__device__ float g_kv   [(size_t)NB * WD * WD];
__device__ float g_y    [(size_t)NB * SP * WD];   // flat [n][s*128+d]

// ============================================================
// Kernel A: theta/phi/g = relu(bn(W @ x))   per batch, per proj
// GEMM: M=128 (channels), N=128-tile of S, K=256
// grid: (S/128, 3, NB), block 256, 8x8 microtile
// ============================================================
__global__ __launch_bounds__(256) void qkv_kernel(
    const float* __restrict__ x,
    const float* __restrict__ w0, const float* __restrict__ w1, const float* __restrict__ w2,
    const float* __restrict__ g1, const float* __restrict__ b1, const float* __restrict__ m1, const float* __restrict__ v1,
    const float* __restrict__ g2, const float* __restrict__ b2, const float* __restrict__ m2, const float* __restrict__ v2,
    const float* __restrict__ g3, const float* __restrict__ b3, const float* __restrict__ m3, const float* __restrict__ v3)
{
    const int proj = blockIdx.y;
    const int n    = blockIdx.z;
    const int s0   = blockIdx.x * 128;
    const int tid  = threadIdx.x;

    const float* w  = (proj == 0) ? w0 : (proj == 1) ? w1 : w2;
    const float* bg = (proj == 0) ? g1 : (proj == 1) ? g2 : g3;
    const float* bb = (proj == 0) ? b1 : (proj == 1) ? b2 : b3;
    const float* bm = (proj == 0) ? m1 : (proj == 1) ? m2 : m3;
    const float* bv = (proj == 0) ? v1 : (proj == 1) ? v2 : v3;
    float* outp = (proj == 0) ? g_theta : (proj == 1) ? g_phi : g_g;

    __shared__ float As[8][136];   // W tile transposed: As[k][m]
    __shared__ float Bs[8][128];   // x tile: Bs[k][s]

    const int tm = (tid >> 4) * 8;     // 0..120  (channel sub-tile)
    const int tn = (tid & 15) * 8;     // 0..120  (spatial sub-tile)

    // load indices
    const int lam = tid >> 1;          // 0..127
    const int lak = (tid & 1) * 4;     // 0 or 4
    const int lbk = tid >> 5;          // 0..7
    const int lbs = (tid & 31) * 4;    // 0..124

    float acc[8][8];
#pragma unroll
    for (int i = 0; i < 8; i++)
#pragma unroll
        for (int j = 0; j < 8; j++) acc[i][j] = 0.f;

    const float* xbase = x + (size_t)n * CIN * SP + s0;

    for (int kt = 0; kt < CIN; kt += 8) {
        float4 wv = *(const float4*)(w + lam * CIN + kt + lak);
        As[lak + 0][lam] = wv.x;
        As[lak + 1][lam] = wv.y;
        As[lak + 2][lam] = wv.z;
        As[lak + 3][lam] = wv.w;
        *(float4*)&Bs[lbk][lbs] = *(const float4*)(xbase + (size_t)(kt + lbk) * SP + lbs);
        __syncthreads();
#pragma unroll
        for (int k = 0; k < 8; k++) {
            float a[8], b[8];
#pragma unroll
            for (int i = 0; i < 8; i++) a[i] = As[k][tm + i];
#pragma unroll
            for (int j = 0; j < 8; j++) b[j] = Bs[k][tn + j];
#pragma unroll
            for (int i = 0; i < 8; i++)
#pragma unroll
                for (int j = 0; j < 8; j++) acc[i][j] = fmaf(a[i], b[j], acc[i][j]);
        }
        __syncthreads();
    }

    float* obase = outp + (size_t)n * WD * SP + s0 + tn;
#pragma unroll
    for (int i = 0; i < 8; i++) {
        const int ch = tm + i;
        const float sc = bg[ch] * rsqrtf(bv[ch] + 1e-5f);
        const float sh = bb[ch] - bm[ch] * sc;
        float4 r0, r1;
        r0.x = fmaxf(fmaf(acc[i][0], sc, sh), 0.f);
        r0.y = fmaxf(fmaf(acc[i][1], sc, sh), 0.f);
        r0.z = fmaxf(fmaf(acc[i][2], sc, sh), 0.f);
        r0.w = fmaxf(fmaf(acc[i][3], sc, sh), 0.f);
        r1.x = fmaxf(fmaf(acc[i][4], sc, sh), 0.f);
        r1.y = fmaxf(fmaf(acc[i][5], sc, sh), 0.f);
        r1.z = fmaxf(fmaf(acc[i][6], sc, sh), 0.f);
        r1.w = fmaxf(fmaf(acc[i][7], sc, sh), 0.f);
        *(float4*)(obase + (size_t)ch * SP)     = r0;
        *(float4*)(obase + (size_t)ch * SP + 4) = r1;
    }
}

// ============================================================
// Kernel B: kv partials.  kvp[n][split][c][d] = sum_{s in chunk} phi[c][s]*g[d][s]
// M=N=128 (one tile), K-chunk=512. grid (KSPLIT, NB)
// ============================================================
__global__ __launch_bounds__(256) void kv_kernel()
{
    const int split = blockIdx.x;
    const int n     = blockIdx.y;
    const int s0    = split * (SP / KSPLIT);
    const int tid   = threadIdx.x;

    __shared__ float As[8][136];   // phi transposed: As[k(s)][c]
    __shared__ float Bs[8][136];   // g   transposed: Bs[k(s)][d]

    const int tm = (tid >> 4) * 8;
    const int tn = (tid & 15) * 8;
    const int lr = tid >> 1;           // row (c or d) 0..127
    const int lk = (tid & 1) * 4;      // k offset 0 or 4

    const float* pbase = g_phi + ((size_t)n * WD + lr) * SP + s0;
    const float* gbase = g_g   + ((size_t)n * WD + lr) * SP + s0;

    float acc[8][8];
#pragma unroll
    for (int i = 0; i < 8; i++)
#pragma unroll
        for (int j = 0; j < 8; j++) acc[i][j] = 0.f;

    for (int kt = 0; kt < SP / KSPLIT; kt += 8) {
        float4 pv = *(const float4*)(pbase + kt + lk);
        float4 gv = *(const float4*)(gbase + kt + lk);
        As[lk + 0][lr] = pv.x; As[lk + 1][lr] = pv.y; As[lk + 2][lr] = pv.z; As[lk + 3][lr] = pv.w;
        Bs[lk + 0][lr] = gv.x; Bs[lk + 1][lr] = gv.y; Bs[lk + 2][lr] = gv.z; Bs[lk + 3][lr] = gv.w;
        __syncthreads();
#pragma unroll
        for (int k = 0; k < 8; k++) {
            float a[8], b[8];
#pragma unroll
            for (int i = 0; i < 8; i++) a[i] = As[k][tm + i];
#pragma unroll
            for (int j = 0; j < 8; j++) b[j] = Bs[k][tn + j];
#pragma unroll
            for (int i = 0; i < 8; i++)
#pragma unroll
                for (int j = 0; j < 8; j++) acc[i][j] = fmaf(a[i], b[j], acc[i][j]);
        }
        __syncthreads();
    }

    float* obase = g_kvp + (((size_t)n * KSPLIT + split) * WD) * WD;
#pragma unroll
    for (int i = 0; i < 8; i++) {
        *(float4*)(obase + (size_t)(tm + i) * WD + tn)     = *(float4*)&acc[i][0];
        *(float4*)(obase + (size_t)(tm + i) * WD + tn + 4) = *(float4*)&acc[i][4];
    }
}

// reduce split-K partials
__global__ __launch_bounds__(256) void kv_reduce()
{
    const int idx = blockIdx.x * 256 + threadIdx.x;   // 0 .. NB*128*128-1
    const int n  = idx >> 14;
    const int cd = idx & 16383;
    float s = 0.f;
#pragma unroll
    for (int k = 0; k < KSPLIT; k++)
        s += g_kvp[((size_t)n * KSPLIT + k) * 16384 + cd];
    g_kv[idx] = s;
}

// ============================================================
// Kernel C: out_flat[n][s*128+d] = sum_c theta[n][c][s] * kv[n][c][d]
// M=128-tile of S, N=128 (d, whole), K=128 (c). grid (S/128, NB)
// ============================================================
__global__ __launch_bounds__(256) void outc_kernel()
{
    const int n   = blockIdx.y;
    const int s0  = blockIdx.x * 128;
    const int tid = threadIdx.x;

    __shared__ float As[8][128];   // theta: As[k(c)][s]  (direct)
    __shared__ float Bs[8][128];   // kv:    Bs[k(c)][d]  (direct)

    const int tm = (tid >> 4) * 8;     // s sub-tile
    const int tn = (tid & 15) * 8;     // d sub-tile
    const int lk = tid >> 5;           // 0..7
    const int lq = (tid & 31) * 4;     // 0..124

    const float* tbase = g_theta + (size_t)n * WD * SP + s0;
    const float* kbase = g_kv    + (size_t)n * WD * WD;

    float acc[8][8];
#pragma unroll
    for (int i = 0; i < 8; i++)
#pragma unroll
        for (int j = 0; j < 8; j++) acc[i][j] = 0.f;

    for (int c0 = 0; c0 < WD; c0 += 8) {
        *(float4*)&As[lk][lq] = *(const float4*)(tbase + (size_t)(c0 + lk) * SP + lq);
        *(float4*)&Bs[lk][lq] = *(const float4*)(kbase + (size_t)(c0 + lk) * WD + lq);
        __syncthreads();
#pragma unroll
        for (int k = 0; k < 8; k++) {
            float a[8], b[8];
#pragma unroll
            for (int i = 0; i < 8; i++) a[i] = As[k][tm + i];
#pragma unroll
            for (int j = 0; j < 8; j++) b[j] = Bs[k][tn + j];
#pragma unroll
            for (int i = 0; i < 8; i++)
#pragma unroll
                for (int j = 0; j < 8; j++) acc[i][j] = fmaf(a[i], b[j], acc[i][j]);
        }
        __syncthreads();
    }

    float* obase = g_y + (size_t)n * SP * WD + (size_t)s0 * WD + tn;
#pragma unroll
    for (int i = 0; i < 8; i++) {
        *(float4*)(obase + (size_t)(tm + i) * WD)     = *(float4*)&acc[i][0];
        *(float4*)(obase + (size_t)(tm + i) * WD + 4) = *(float4*)&acc[i][4];
    }
}

// ============================================================
// Kernel D: z = relu(bn4(w_zeta @ y) + x)
// y[n][w][s] = g_y flat at w*4096+s (the "reshape"). M=256 (o), N=S, K=128 (w)
// grid (S/128, 2, NB)
// ============================================================
__global__ __launch_bounds__(256) void zeta_kernel(
    const float* __restrict__ x, const float* __restrict__ wz,
    const float* __restrict__ g4, const float* __restrict__ b4,
    const float* __restrict__ m4, const float* __restrict__ v4,
    float* __restrict__ out)
{
    const int n   = blockIdx.z;
    const int o0  = blockIdx.y * 128;
    const int s0  = blockIdx.x * 128;
    const int tid = threadIdx.x;

    __shared__ float As[8][136];   // wz transposed: As[k(w)][o]
    __shared__ float Bs[8][128];   // y: Bs[k(w)][s]

    const int tm = (tid >> 4) * 8;     // o sub-tile
    const int tn = (tid & 15) * 8;     // s sub-tile
    const int lam = tid >> 1;
    const int lak = (tid & 1) * 4;
    const int lbk = tid >> 5;
    const int lbs = (tid & 31) * 4;

    const float* ybase = g_y + (size_t)n * SP * WD + s0;   // read as [w][s]: w*SP + s

    float acc[8][8];
#pragma unroll
    for (int i = 0; i < 8; i++)
#pragma unroll
        for (int j = 0; j < 8; j++) acc[i][j] = 0.f;

    for (int k0 = 0; k0 < WD; k0 += 8) {
        float4 wv = *(const float4*)(wz + (size_t)(o0 + lam) * WD + k0 + lak);
        As[lak + 0][lam] = wv.x;
        As[lak + 1][lam] = wv.y;
        As[lak + 2][lam] = wv.z;
        As[lak + 3][lam] = wv.w;
        *(float4*)&Bs[lbk][lbs] = *(const float4*)(ybase + (size_t)(k0 + lbk) * SP + lbs);
        __syncthreads();
#pragma unroll
        for (int k = 0; k < 8; k++) {
            float a[8], b[8];
#pragma unroll
            for (int i = 0; i < 8; i++) a[i] = As[k][tm + i];
#pragma unroll
            for (int j = 0; j < 8; j++) b[j] = Bs[k][tn + j];
#pragma unroll
            for (int i = 0; i < 8; i++)
#pragma unroll
                for (int j = 0; j < 8; j++) acc[i][j] = fmaf(a[i], b[j], acc[i][j]);
        }
        __syncthreads();
    }

    const float* xbase = x   + (size_t)n * CIN * SP + s0 + tn;
    float*       obase = out + (size_t)n * CIN * SP + s0 + tn;
#pragma unroll
    for (int i = 0; i < 8; i++) {
        const int ch = o0 + tm + i;
        const float sc = g4[ch] * rsqrtf(v4[ch] + 1e-5f);
        const float sh = b4[ch] - m4[ch] * sc;
        float4 x0 = *(const float4*)(xbase + (size_t)ch * SP);
        float4 x1 = *(const float4*)(xbase + (size_t)ch * SP + 4);
        float4 r0, r1;
        r0.x = fmaxf(fmaf(acc[i][0], sc, sh) + x0.x, 0.f);
        r0.y = fmaxf(fmaf(acc[i][1], sc, sh) + x0.y, 0.f);
        r0.z = fmaxf(fmaf(acc[i][2], sc, sh) + x0.z, 0.f);
        r0.w = fmaxf(fmaf(acc[i][3], sc, sh) + x0.w, 0.f);
        r1.x = fmaxf(fmaf(acc[i][4], sc, sh) + x1.x, 0.f);
        r1.y = fmaxf(fmaf(acc[i][5], sc, sh) + x1.y, 0.f);
        r1.z = fmaxf(fmaf(acc[i][6], sc, sh) + x1.z, 0.f);
        r1.w = fmaxf(fmaf(acc[i][7], sc, sh) + x1.w, 0.f);
        *(float4*)(obase + (size_t)ch * SP)     = r0;
        *(float4*)(obase + (size_t)ch * SP + 4) = r1;
    }
}

// ============================================================
extern "C" void kernel_launch(void* const* d_in, const int* in_sizes, int n_in,
                              void* d_out, int out_size)
{
    const float* x       = (const float*)d_in[0];
    const float* w_theta = (const float*)d_in[1];
    const float* w_phi   = (const float*)d_in[2];
    const float* w_g     = (const float*)d_in[3];
    const float* w_zeta  = (const float*)d_in[4];
    const float* bn1g = (const float*)d_in[5],  *bn1b = (const float*)d_in[6],
               * bn1m = (const float*)d_in[7],  *bn1v = (const float*)d_in[8];
    const float* bn2g = (const float*)d_in[9],  *bn2b = (const float*)d_in[10],
               * bn2m = (const float*)d_in[11], *bn2v = (const float*)d_in[12];
    const float* bn3g = (const float*)d_in[13], *bn3b = (const float*)d_in[14],
               * bn3m = (const float*)d_in[15], *bn3v = (const float*)d_in[16];
    const float* bn4g = (const float*)d_in[17], *bn4b = (const float*)d_in[18],
               * bn4m = (const float*)d_in[19], *bn4v = (const float*)d_in[20];
    float* out = (float*)d_out;

    dim3 gA(SP / 128, 3, NB);
    qkv_kernel<<<gA, 256>>>(x, w_theta, w_phi, w_g,
                            bn1g, bn1b, bn1m, bn1v,
                            bn2g, bn2b, bn2m, bn2v,
                            bn3g, bn3b, bn3m, bn3v);

    dim3 gB(KSPLIT, NB);
    kv_kernel<<<gB, 256>>>();

    kv_reduce<<<(NB * WD * WD) / 256, 256>>>();

    dim3 gC(SP / 128, NB);
    outc_kernel<<<gC, 256>>>();

    dim3 gD(SP / 128, CIN / 128, NB);
    zeta_kernel<<<gD, 256>>>(x, w_zeta, bn4g, bn4b, bn4m, bn4v, out);
}